// round 15
// baseline (speedup 1.0000x reference)
#include <cuda_runtime.h>
#include <cuda_fp16.h>
#include <math.h>

// ---------------------------------------------------------------------------
// EvidentialGNN3D — geo-precomputed, round-0 fused into build, round-2 fused
// into graph readout (REDs go to the hot per-graph table, not per-node state).
//  rec[e] = { dot1 f32, dot2 f32, len(f16)|dst_lo16, src(18b)|dst_hi2|g(11b) }
//  k_geo0  : gather pc[f],pc[t] (32B rows incl. gidx); geo; rec; round-0 msg
//            m0 = tanh(geo@Wg + b + sa_f*W11); vector-RED into state[dst].
//  round 1 : k_h + k_edge (REDs into state).
//  round 2 : k_h + k_edge_g (REDs into g_gs[g] — hot 96KB table).
//  readout : k_graph adds state^2 rows into g_gs; k_out head.
// ---------------------------------------------------------------------------

#define NMAX 200064
#define EMAX 6400000
#define GMAX 2048
#define SDP  12

struct __align__(32) HRow  { uint4 a; uint2 b; uint2 pad; };
struct __align__(32) PCRow { float4 p; int g; int pad0, pad1, pad2; };

__device__ float4 g_state[NMAX * 3];   // (N,12) state, updated in place
__device__ HRow   g_hp[NMAX];          // h packed: 10 x fp16 in one 32B sector
__device__ PCRow  g_pc[NMAX];          // (x,y,z,sum|c|, gidx) one 32B sector
__device__ float4 g_gs[GMAX * 3];      // per-graph accum (hot, 96KB)
__device__ uint4  g_rec[EMAX];         // packed records
__device__ float  g_w[30];             // W rows 10 (len), 12 (dot1), 13 (dot2)

__device__ __forceinline__ float tanh_fast(float x) {
    float e = __expf(2.0f * x);
    return 1.0f - __fdividef(2.0f, e + 1.0f);
}
__device__ __forceinline__ void red_add4(float* p, float a, float b, float c, float d) {
    unsigned long long gp = __cvta_generic_to_global((void*)p);
    asm volatile("red.global.add.v4.f32 [%0], {%1,%2,%3,%4};"
                 :: "l"(gp), "f"(a), "f"(b), "f"(c), "f"(d) : "memory");
}
__device__ __forceinline__ void red_add2(float* p, float a, float b) {
    unsigned long long gp = __cvta_generic_to_global((void*)p);
    asm volatile("red.global.add.v2.f32 [%0], {%1,%2};"
                 :: "l"(gp), "f"(a), "f"(b) : "memory");
}

__device__ __forceinline__ void store_h(int n, const float* h) {
    __half2 p0 = __floats2half2_rn(h[0], h[1]);
    __half2 p1 = __floats2half2_rn(h[2], h[3]);
    __half2 p2 = __floats2half2_rn(h[4], h[5]);
    __half2 p3 = __floats2half2_rn(h[6], h[7]);
    __half2 p4 = __floats2half2_rn(h[8], h[9]);
    HRow r;
    r.a.x = *(unsigned int*)&p0;
    r.a.y = *(unsigned int*)&p1;
    r.a.z = *(unsigned int*)&p2;
    r.a.w = *(unsigned int*)&p3;
    r.b.x = *(unsigned int*)&p4;
    r.b.y = 0u;
    r.pad.x = 0u; r.pad.y = 0u;
    g_hp[n] = r;
}

// ---- init: pc(+gidx), zero state & graph accum, stash edge-weight rows ----
__global__ void k_init(const float* __restrict__ coords,
                       const int* __restrict__ gidx,
                       const float* __restrict__ Wm, int N) {
    int n = blockIdx.x * blockDim.x + threadIdx.x;
    float4 z4 = make_float4(0.f, 0.f, 0.f, 0.f);
    if (n < N) {
        float x = coords[3 * n + 0];
        float y = coords[3 * n + 1];
        float z = coords[3 * n + 2];
        float sa = fabsf(x) + fabsf(y) + fabsf(z);
        PCRow pr;
        pr.p = make_float4(x, y, z, sa);
        pr.g = __ldg(&gidx[n]);
        pr.pad0 = 0; pr.pad1 = 0; pr.pad2 = 0;
        g_pc[n] = pr;
        g_state[n * 3 + 0] = z4;
        g_state[n * 3 + 1] = z4;
        g_state[n * 3 + 2] = z4;
    }
    if (n < GMAX) {
        g_gs[n * 3 + 0] = z4;
        g_gs[n * 3 + 1] = z4;
        g_gs[n * 3 + 2] = z4;
    }
    if (blockIdx.x == 0 && threadIdx.x < 10) {
        int j = threadIdx.x;
        g_w[j]      = __ldg(&Wm[100 + j]);
        g_w[10 + j] = __ldg(&Wm[120 + j]);
        g_w[20 + j] = __ldg(&Wm[130 + j]);
    }
}

// ---- fused build + round 0 ----
__global__ void __launch_bounds__(256)
k_geo0(const int* __restrict__ efrom, const int* __restrict__ eto,
       const float* __restrict__ elen, const float* __restrict__ evec,
       const float* __restrict__ Wm, const float* __restrict__ bm,
       int E, int T) {
    int tid = blockIdx.x * blockDim.x + threadIdx.x;
    float wl[10], w2[10], w3[10], w11[10], bb[10];
#pragma unroll
    for (int j = 0; j < 10; j++) {
        wl[j]  = __ldg(&Wm[100 + j]);
        w2[j]  = __ldg(&Wm[120 + j]);
        w3[j]  = __ldg(&Wm[130 + j]);
        w11[j] = __ldg(&Wm[110 + j]);
        bb[j]  = __ldg(&bm[j]);
    }
    float* stt = (float*)g_state;
    for (int e = tid; e < E; e += T) {
        int f = __ldcs(&efrom[e]);
        int t = __ldcs(&eto[e]);
        float4 cf = g_pc[f].p;
        float4 ct = g_pc[t].p;
        int    gt = g_pc[t].g;           // same 32B sector as ct — free
        float len = __ldcs(&elen[e]);
        float v0 = __ldcs(&evec[3 * e + 0]);
        float v1 = __ldcs(&evec[3 * e + 1]);
        float v2 = __ldcs(&evec[3 * e + 2]);
        float dot1 = fmaf(cf.x, ct.x, fmaf(cf.y, ct.y, cf.z * ct.z));
        float dot2 = fmaf(cf.x, v0, fmaf(cf.y, v1, cf.z * v2));
        uint4 r;
        r.x = __float_as_uint(dot1);
        r.y = __float_as_uint(dot2);
        r.z = (unsigned int)__half_as_ushort(__float2half_rn(len))
            | (((unsigned int)t & 0xFFFFu) << 16);
        r.w = (unsigned int)f | (((unsigned int)t >> 16) << 18)
            | ((unsigned int)gt << 20);
        __stcs(&g_rec[e], r);
        // round-0 message: h0 = b + sa*W11, all local
        float sa = cf.w;
        float m[10];
#pragma unroll
        for (int j = 0; j < 10; j++) {
            float h0 = fmaf(sa, w11[j], bb[j]);
            float a = fmaf(len, wl[j], fmaf(dot1, w2[j], fmaf(dot2, w3[j], h0)));
            m[j] = tanh_fast(a);
        }
        float* dst = stt + (size_t)t * SDP;
        red_add4(dst,     m[0], m[1], m[2], m[3]);
        red_add4(dst + 4, m[4], m[5], m[6], m[7]);
        red_add2(dst + 8, m[8], m[9]);
    }
}

// ---- per-node h = state@Ws + b + sa*W11 (fp16-packed) ----
__global__ void k_h(const float* __restrict__ Wm, const float* __restrict__ bm,
                    int N) {
    int n = blockIdx.x * blockDim.x + threadIdx.x;
    if (n >= N) return;
    const float4* srow = &g_state[n * 3];
    float4 s0 = srow[0], s1 = srow[1], s2 = srow[2];
    float s[10] = { s0.x, s0.y, s0.z, s0.w, s1.x, s1.y, s1.z, s1.w, s2.x, s2.y };
    float sa = g_pc[n].p.w;
    float h[10];
#pragma unroll
    for (int j = 0; j < 10; j++) {
        float acc = fmaf(sa, __ldg(&Wm[110 + j]), __ldg(&bm[j]));
#pragma unroll
        for (int i = 0; i < 10; i++)
            acc = fmaf(s[i], __ldg(&Wm[i * 10 + j]), acc);
        h[j] = acc;
    }
    store_h(n, h);
}

// ---- round-1 edge pass: REDs into per-node state ----
__global__ void __launch_bounds__(256)
k_edge(int E, int T) {
    int tid = blockIdx.x * blockDim.x + threadIdx.x;
    float wl[10], w2[10], w3[10];
#pragma unroll
    for (int j = 0; j < 10; j++) {
        wl[j] = g_w[j];
        w2[j] = g_w[10 + j];
        w3[j] = g_w[20 + j];
    }
    float* stt = (float*)g_state;
    for (int e = tid; e < E; e += T) {
        uint4 r = __ldcs(&g_rec[e]);
        float dot1 = __uint_as_float(r.x);
        float dot2 = __uint_as_float(r.y);
        float len = __half2float(__ushort_as_half((unsigned short)(r.z & 0xFFFFu)));
        int t = (int)(r.z >> 16) | (int)(((r.w >> 18) & 3u) << 16);
        int f = (int)(r.w & 0x3FFFFu);
        const HRow* hp = &g_hp[f];
        uint4 u = __ldg(&hp->a);
        uint2 v = __ldg(&hp->b);
        float2 a0 = __half22float2(*(__half2*)&u.x);
        float2 a1 = __half22float2(*(__half2*)&u.y);
        float2 a2 = __half22float2(*(__half2*)&u.z);
        float2 a3 = __half22float2(*(__half2*)&u.w);
        float2 a4 = __half22float2(*(__half2*)&v.x);
        float hv[10] = { a0.x, a0.y, a1.x, a1.y, a2.x, a2.y, a3.x, a3.y, a4.x, a4.y };
        float m[10];
#pragma unroll
        for (int j = 0; j < 10; j++) {
            float a = fmaf(len, wl[j], fmaf(dot1, w2[j], fmaf(dot2, w3[j], hv[j])));
            m[j] = tanh_fast(a);
        }
        float* dst = stt + (size_t)t * SDP;
        red_add4(dst,     m[0], m[1], m[2], m[3]);
        red_add4(dst + 4, m[4], m[5], m[6], m[7]);
        red_add2(dst + 8, m[8], m[9]);
    }
}

// ---- round-2 edge pass: REDs straight into the per-graph table ----
__global__ void __launch_bounds__(256)
k_edge_g(int E, int T) {
    int tid = blockIdx.x * blockDim.x + threadIdx.x;
    float wl[10], w2[10], w3[10];
#pragma unroll
    for (int j = 0; j < 10; j++) {
        wl[j] = g_w[j];
        w2[j] = g_w[10 + j];
        w3[j] = g_w[20 + j];
    }
    float* gst = (float*)g_gs;
    for (int e = tid; e < E; e += T) {
        uint4 r = __ldcs(&g_rec[e]);
        float dot1 = __uint_as_float(r.x);
        float dot2 = __uint_as_float(r.y);
        float len = __half2float(__ushort_as_half((unsigned short)(r.z & 0xFFFFu)));
        int g = (int)(r.w >> 20);
        int f = (int)(r.w & 0x3FFFFu);
        const HRow* hp = &g_hp[f];
        uint4 u = __ldg(&hp->a);
        uint2 v = __ldg(&hp->b);
        float2 a0 = __half22float2(*(__half2*)&u.x);
        float2 a1 = __half22float2(*(__half2*)&u.y);
        float2 a2 = __half22float2(*(__half2*)&u.z);
        float2 a3 = __half22float2(*(__half2*)&u.w);
        float2 a4 = __half22float2(*(__half2*)&v.x);
        float hv[10] = { a0.x, a0.y, a1.x, a1.y, a2.x, a2.y, a3.x, a3.y, a4.x, a4.y };
        float m[10];
#pragma unroll
        for (int j = 0; j < 10; j++) {
            float a = fmaf(len, wl[j], fmaf(dot1, w2[j], fmaf(dot2, w3[j], hv[j])));
            m[j] = tanh_fast(a);
        }
        float* dst = gst + (size_t)g * SDP;
        red_add4(dst,     m[0], m[1], m[2], m[3]);
        red_add4(dst + 4, m[4], m[5], m[6], m[7]);
        red_add2(dst + 8, m[8], m[9]);
    }
}

// ---- graph segment sum of state^2 (round-2 messages added by k_edge_g) ----
__global__ void k_graph(int N) {
    int n = blockIdx.x * blockDim.x + threadIdx.x;
    if (n >= N) return;
    int g = g_pc[n].g;
    const float4* srow = &g_state[n * 3];
    float4 s0 = srow[0], s1 = srow[1], s2 = srow[2];
    float* dst = (float*)&g_gs[g * 3];
    red_add4(dst,     s0.x, s0.y, s0.z, s0.w);
    red_add4(dst + 4, s1.x, s1.y, s1.z, s1.w);
    red_add2(dst + 8, s2.x, s2.y);
}

__device__ __forceinline__ float softplus_acc(float x) {
    if (x > 20.f) return x;
    return log1pf(expf(x));
}

__global__ void k_out(const float* __restrict__ Wo, const float* __restrict__ bo,
                      float* __restrict__ out, int G) {
    int g = blockIdx.x * blockDim.x + threadIdx.x;
    if (g >= G) return;
    const float* gs = (const float*)&g_gs[g * 3];
    float e[4];
#pragma unroll
    for (int j = 0; j < 4; j++) {
        float acc = __ldg(&bo[j]);
#pragma unroll
        for (int i = 0; i < 10; i++)
            acc = fmaf(gs[i], __ldg(&Wo[i * 4 + j]), acc);
        e[j] = acc;
    }
    out[4 * g + 0] = e[0];
    out[4 * g + 1] = softplus_acc(e[1]);
    out[4 * g + 2] = softplus_acc(e[2]) + 1.0f;
    out[4 * g + 3] = softplus_acc(e[3]);
}

extern "C" void kernel_launch(void* const* d_in, const int* in_sizes, int n_in,
                              void* d_out, int out_size) {
    const float* coords = (const float*)d_in[0];
    const float* elen   = (const float*)d_in[1];
    const float* evec   = (const float*)d_in[2];
    const float* Wm     = (const float*)d_in[3];
    const float* bm     = (const float*)d_in[4];
    const float* Wo     = (const float*)d_in[5];
    const float* bo     = (const float*)d_in[6];
    const int*   efrom  = (const int*)d_in[7];
    const int*   eto    = (const int*)d_in[8];
    const int*   gidx   = (const int*)d_in[9];
    float* out = (float*)d_out;

    int E = in_sizes[7];
    int N = in_sizes[9];
    int G = out_size / 4;

    const int TB = 256;
    int init_count = (N > GMAX) ? N : GMAX;
    int init_blocks = (init_count + TB - 1) / TB;
    int node_blocks = (N + TB - 1) / TB;
    long ethreads = ((long)E + 3) / 4;              // 4 edges/thread
    int eblocks = (int)((ethreads + TB - 1) / TB);
    int T = eblocks * TB;
    int gblocks = (G + TB - 1) / TB;

    k_init<<<init_blocks, TB>>>(coords, gidx, Wm, N);
    // round 0 fused with build
    k_geo0<<<eblocks, TB>>>(efrom, eto, elen, evec, Wm, bm, E, T);
    // round 1
    k_h<<<node_blocks, TB>>>(Wm, bm, N);
    k_edge<<<eblocks, TB>>>(E, T);
    // round 2: messages go straight to the per-graph table
    k_h<<<node_blocks, TB>>>(Wm, bm, N);
    k_edge_g<<<eblocks, TB>>>(E, T);
    // add state^2 rows into the per-graph table, then head
    k_graph<<<node_blocks, TB>>>(N);
    k_out<<<gblocks, TB>>>(Wo, bo, out, G);
}